// round 1
// baseline (speedup 1.0000x reference)
#include <cuda_runtime.h>
#include <cuda_bf16.h>

#define TPB 256
#define EPT 16   // elements per thread; TPB*EPT == T == 4096

// Flag decided by the probe kernel: 1 => idx_mask buffer holds int32 0/1,
// 0 => it holds 1-byte bools.
__device__ int g_idx_is_int32;

// Inspect the first `nbytes` of the idx_mask buffer. If the data is int32
// 0/1 flags (little-endian), every byte at (pos % 4 != 0) is zero. If it's
// 1-byte bools at ~5% density, thousands of those bytes are nonzero.
__global__ void probe_kernel(const unsigned char* __restrict__ p, int nbytes) {
    __shared__ int cnt;
    if (threadIdx.x == 0) cnt = 0;
    __syncthreads();
    int local = 0;
    for (int i = threadIdx.x; i < nbytes; i += blockDim.x)
        if ((i & 3) != 0 && p[i] != 0) local++;
    if (local) atomicAdd(&cnt, local);
    __syncthreads();
    if (threadIdx.x == 0) g_idx_is_int32 = (cnt == 0) ? 1 : 0;
}

__global__ __launch_bounds__(TPB) void seg_mask_kernel(
    const float* __restrict__ x,
    const unsigned char* __restrict__ idx8,   // bool OR int32 flags, per g_idx_is_int32
    const int* __restrict__ mask_size,        // [S]
    const int* __restrict__ mask_value,       // scalar
    float* __restrict__ out,                  // [rows*T]
    float* __restrict__ mask_out,             // [rows*T] or nullptr
    int S, int T)
{
    const int row  = blockIdx.x;            // row = b*S + s
    const int s    = row % S;
    const int m    = mask_size[s];
    const float mv = (float)mask_value[0];
    const long long base = (long long)row * T;
    const int tid = threadIdx.x;
    const int t0  = tid * EPT;

    // ---- load 16 flags for this thread's chunk ----
    unsigned char fb[EPT];
    if (g_idx_is_int32) {
        const int4* ip = (const int4*)((const int*)idx8 + base + t0);
        #pragma unroll
        for (int j = 0; j < 4; j++) {
            int4 v = ip[j];
            fb[j*4+0] = (unsigned char)(v.x != 0);
            fb[j*4+1] = (unsigned char)(v.y != 0);
            fb[j*4+2] = (unsigned char)(v.z != 0);
            fb[j*4+3] = (unsigned char)(v.w != 0);
        }
    } else {
        uint4 v = *(const uint4*)(idx8 + base + t0);
        unsigned int w[4] = {v.x, v.y, v.z, v.w};
        #pragma unroll
        for (int i = 0; i < EPT; i++)
            fb[i] = (unsigned char)((w[i >> 2] >> ((i & 3) * 8)) & 0xFF);
    }

    // ---- local "last start index" within chunk ----
    int local_last = -1;
    #pragma unroll
    for (int i = 0; i < EPT; i++)
        if (fb[i]) local_last = t0 + i;

    // ---- block-wide exclusive max-scan over per-thread local_last ----
    int v = local_last;
    const int lane = tid & 31, wid = tid >> 5;
    #pragma unroll
    for (int off = 1; off < 32; off <<= 1) {
        int u = __shfl_up_sync(0xffffffffu, v, off);
        if (lane >= off) v = max(v, u);
    }
    __shared__ int wmax[TPB / 32];
    if (lane == 31) wmax[wid] = v;
    __syncthreads();
    int incl_prev = __shfl_up_sync(0xffffffffu, v, 1);  // inclusive scan of lane-1
    int excl = (lane == 0) ? -1 : incl_prev;
    #pragma unroll
    for (int w = 0; w < TPB / 32; w++)
        if (w < wid) excl = max(excl, wmax[w]);

    // ---- compute out / mask with carried last-start ----
    const float4* xv = (const float4*)(x + base + t0);
    float4* ov = (float4*)(out + base + t0);
    float4* mov = mask_out ? (float4*)(mask_out + base + t0) : nullptr;

    int cur = excl;
    #pragma unroll
    for (int j = 0; j < 4; j++) {
        float4 xx = xv[j];
        const float* xa = (const float*)&xx;
        float o[4], mk[4];
        #pragma unroll
        for (int i = 0; i < 4; i++) {
            int t = t0 + j * 4 + i;
            if (fb[j * 4 + i]) cur = t;
            int lo = t - m; if (lo < 0) lo = 0;
            bool msk = (cur >= lo);          // cur == -1 always fails (lo >= 0)
            mk[i] = msk ? 1.0f : 0.0f;
            o[i]  = msk ? mv : xa[i];
        }
        float4 ot = {o[0], o[1], o[2], o[3]};
        ov[j] = ot;
        if (mov) { float4 mt = {mk[0], mk[1], mk[2], mk[3]}; mov[j] = mt; }
    }
}

extern "C" void kernel_launch(void* const* d_in, const int* in_sizes, int n_in,
                              void* d_out, int out_size) {
    const float*         x     = (const float*)d_in[0];
    const unsigned char* idx   = (const unsigned char*)d_in[1];
    const int*           msize = (const int*)d_in[2];
    const int*           mval  = (const int*)d_in[3];
    float* out = (float*)d_out;

    const int T = 4096;
    const int N = in_sizes[0];          // B*S*T
    const int S = in_sizes[2];          // 128
    const int rows = N / T;             // B*S = 8192

    // Tuple output (out, mask) -> concatenated float32 if out_size covers both.
    float* mask_out = (out_size >= 2 * N) ? (out + (long long)N) : nullptr;

    probe_kernel<<<1, 256>>>(idx, 65536);
    seg_mask_kernel<<<rows, TPB>>>(x, idx, msize, mval, out, mask_out, S, T);
}

// round 2
// speedup vs baseline: 2.0703x; 2.0703x over previous
#include <cuda_runtime.h>
#include <cuda_bf16.h>

#define TPB 256
#define EPT 16   // elements per thread; TPB*EPT == T == 4096

// Flag decided by the probe kernel: 1 => idx_mask buffer holds int32 0/1,
// 0 => it holds 1-byte bools.
__device__ int g_idx_is_int32;

// Vectorized probe: if the buffer is int32 0/1 flags (little-endian), all
// bytes except byte 0 of each word are zero -> (w & 0xFFFFFF00) == 0 for
// every word. 5%-dense bools violate this thousands of times in 64KB.
__global__ void probe_kernel(const uint4* __restrict__ p, int nvec) {
    int local = 0;
    for (int i = threadIdx.x; i < nvec; i += blockDim.x) {
        uint4 v = p[i];
        local |= (v.x & 0xFFFFFF00u) | (v.y & 0xFFFFFF00u) |
                 (v.z & 0xFFFFFF00u) | (v.w & 0xFFFFFF00u);
    }
    int any = __syncthreads_or(local != 0);
    if (threadIdx.x == 0) g_idx_is_int32 = any ? 0 : 1;
}

__global__ __launch_bounds__(TPB) void seg_mask_kernel(
    const float* __restrict__ x,
    const unsigned char* __restrict__ idx8,   // bool OR int32 flags, per g_idx_is_int32
    const int* __restrict__ mask_size,        // [S]
    const int* __restrict__ mask_value,       // scalar
    float* __restrict__ out,                  // [rows*T]
    float* __restrict__ mask_out,             // [rows*T] or nullptr
    int S, int T)
{
    const int row  = blockIdx.x;            // row = b*S + s
    const int s    = row % S;
    const long long base = (long long)row * T;
    const int tid = threadIdx.x;
    const int t0  = tid * EPT;

    // ---- front-batch ALL loads (flags + x) for max MLP ----
    unsigned int bits;        // bit i = flag at t0+i  (16 bits used)
    float4 xx0, xx1, xx2, xx3;
    const float4* xv = (const float4*)(x + base + t0);

    if (g_idx_is_int32) {
        const int4* ip = (const int4*)((const int*)idx8 + base + t0);
        int4 a = __ldcs(ip + 0);
        int4 b = __ldcs(ip + 1);
        int4 c = __ldcs(ip + 2);
        int4 d = __ldcs(ip + 3);
        xx0 = __ldcs(xv + 0); xx1 = __ldcs(xv + 1);
        xx2 = __ldcs(xv + 2); xx3 = __ldcs(xv + 3);
        bits  = ((unsigned)(a.x != 0) <<  0) | ((unsigned)(a.y != 0) <<  1)
              | ((unsigned)(a.z != 0) <<  2) | ((unsigned)(a.w != 0) <<  3)
              | ((unsigned)(b.x != 0) <<  4) | ((unsigned)(b.y != 0) <<  5)
              | ((unsigned)(b.z != 0) <<  6) | ((unsigned)(b.w != 0) <<  7)
              | ((unsigned)(c.x != 0) <<  8) | ((unsigned)(c.y != 0) <<  9)
              | ((unsigned)(c.z != 0) << 10) | ((unsigned)(c.w != 0) << 11)
              | ((unsigned)(d.x != 0) << 12) | ((unsigned)(d.y != 0) << 13)
              | ((unsigned)(d.z != 0) << 14) | ((unsigned)(d.w != 0) << 15);
    } else {
        uint4 v = __ldcs((const uint4*)(idx8 + base + t0));
        xx0 = __ldcs(xv + 0); xx1 = __ldcs(xv + 1);
        xx2 = __ldcs(xv + 2); xx3 = __ldcs(xv + 3);
        // per-byte nonzero -> 0/1 per byte, then gather 4 bits via mul trick:
        // m = b0 | b1<<8 | b2<<16 | b3<<24 ; (m * 0x01020408) >> 24 = b0|b1<<1|b2<<2|b3<<3
        unsigned m0 = __vcmpne4(v.x, 0u) & 0x01010101u;
        unsigned m1 = __vcmpne4(v.y, 0u) & 0x01010101u;
        unsigned m2 = __vcmpne4(v.z, 0u) & 0x01010101u;
        unsigned m3 = __vcmpne4(v.w, 0u) & 0x01010101u;
        bits  = ((m0 * 0x01020408u) >> 24)
              | (((m1 * 0x01020408u) >> 24) << 4)
              | (((m2 * 0x01020408u) >> 24) << 8)
              | (((m3 * 0x01020408u) >> 24) << 12);
    }

    const int m  = mask_size[s];
    const float mv = (float)mask_value[0];

    // ---- local "last start index" within chunk (from bitmask) ----
    int local_last = bits ? (t0 + 31 - __clz(bits)) : -1;

    // ---- block-wide exclusive max-scan over per-thread local_last ----
    int v = local_last;
    const int lane = tid & 31, wid = tid >> 5;
    #pragma unroll
    for (int off = 1; off < 32; off <<= 1) {
        int u = __shfl_up_sync(0xffffffffu, v, off);
        if (lane >= off) v = max(v, u);
    }
    __shared__ int wmax[TPB / 32];
    if (lane == 31) wmax[wid] = v;
    __syncthreads();
    int incl_prev = __shfl_up_sync(0xffffffffu, v, 1);  // inclusive scan of lane-1
    int excl = (lane == 0) ? -1 : incl_prev;
    #pragma unroll
    for (int w = 0; w < TPB / 32; w++)
        if (w < wid) excl = max(excl, wmax[w]);

    // ---- compute out / mask with carried last-start ----
    float4* ov = (float4*)(out + base + t0);
    float4* mov = mask_out ? (float4*)(mask_out + base + t0) : nullptr;

    float4 xr[4] = {xx0, xx1, xx2, xx3};
    int cur = excl;
    #pragma unroll
    for (int j = 0; j < 4; j++) {
        const float* xa = (const float*)&xr[j];
        float o[4], mk[4];
        #pragma unroll
        for (int i = 0; i < 4; i++) {
            int k = j * 4 + i;
            int t = t0 + k;
            if ((bits >> k) & 1u) cur = t;
            int lo = t - m; if (lo < 0) lo = 0;
            bool msk = (cur >= lo);          // cur == -1 always fails (lo >= 0)
            mk[i] = msk ? 1.0f : 0.0f;
            o[i]  = msk ? mv : xa[i];
        }
        float4 ot = {o[0], o[1], o[2], o[3]};
        __stcs(ov + j, ot);
        if (mov) { float4 mt = {mk[0], mk[1], mk[2], mk[3]}; __stcs(mov + j, mt); }
    }
}

extern "C" void kernel_launch(void* const* d_in, const int* in_sizes, int n_in,
                              void* d_out, int out_size) {
    const float*         x     = (const float*)d_in[0];
    const unsigned char* idx   = (const unsigned char*)d_in[1];
    const int*           msize = (const int*)d_in[2];
    const int*           mval  = (const int*)d_in[3];
    float* out = (float*)d_out;

    const int T = 4096;
    const int N = in_sizes[0];          // B*S*T
    const int S = in_sizes[2];          // 128
    const int rows = N / T;             // B*S = 8192

    // Tuple output (out, mask) -> concatenated float32 if out_size covers both.
    float* mask_out = (out_size >= 2 * N) ? (out + (long long)N) : nullptr;

    probe_kernel<<<1, 1024>>>((const uint4*)idx, 65536 / 16);
    seg_mask_kernel<<<rows, TPB>>>(x, idx, msize, mval, out, mask_out, S, T);
}

// round 3
// speedup vs baseline: 2.2600x; 1.0916x over previous
#include <cuda_runtime.h>
#include <cuda_bf16.h>

#define TPB 512
#define EPT 8    // elements per thread; TPB*EPT == T == 4096
#define NWARP (TPB / 32)

// Flag decided by the probe kernel: 1 => idx_mask buffer holds int32 0/1,
// 0 => it holds 1-byte bools.
__device__ int g_idx_is_int32;

// Minimal vectorized probe over the first 4KB: int32 0/1 flags have every
// byte at (pos % 4 != 0) equal to zero -> (w & 0xFFFFFF00) == 0 for every
// word. 5%-dense bool bytes violate this ~150 times in 4KB.
__global__ void probe_kernel(const uint4* __restrict__ p) {
    uint4 v = p[threadIdx.x];                 // 256 threads x 16B = 4KB
    unsigned local = (v.x & 0xFFFFFF00u) | (v.y & 0xFFFFFF00u) |
                     (v.z & 0xFFFFFF00u) | (v.w & 0xFFFFFF00u);
    int any = __syncthreads_or(local != 0);
    if (threadIdx.x == 0) g_idx_is_int32 = any ? 0 : 1;
}

__global__ __launch_bounds__(TPB) void seg_mask_kernel(
    const float* __restrict__ x,
    const unsigned char* __restrict__ idx8,   // bool OR int32 flags, per g_idx_is_int32
    const int* __restrict__ mask_size,        // [S]
    const int* __restrict__ mask_value,       // scalar
    float* __restrict__ out,                  // [rows*T]
    float* __restrict__ mask_out,             // [rows*T] or nullptr
    int S, int T)
{
    const int row  = blockIdx.x;             // row = b*S + s
    const int s    = row % S;
    const long long base = (long long)row * T;
    const int tid = threadIdx.x;
    const int t0  = tid * EPT;

    // ---- front-batch ALL loads (flags + x) ----
    unsigned int bits;                        // bit i = flag at t0+i (8 bits used)
    float4 xx0, xx1;
    const float4* xv = (const float4*)(x + base + t0);

    if (g_idx_is_int32) {
        const int4* ip = (const int4*)((const int*)idx8 + base + t0);
        int4 a = __ldcs(ip + 0);
        int4 b = __ldcs(ip + 1);
        xx0 = __ldcs(xv + 0); xx1 = __ldcs(xv + 1);
        bits  = ((unsigned)(a.x != 0) << 0) | ((unsigned)(a.y != 0) << 1)
              | ((unsigned)(a.z != 0) << 2) | ((unsigned)(a.w != 0) << 3)
              | ((unsigned)(b.x != 0) << 4) | ((unsigned)(b.y != 0) << 5)
              | ((unsigned)(b.z != 0) << 6) | ((unsigned)(b.w != 0) << 7);
    } else {
        uint2 v = __ldcs((const uint2*)(idx8 + base + t0));
        xx0 = __ldcs(xv + 0); xx1 = __ldcs(xv + 1);
        unsigned m0 = __vcmpne4(v.x, 0u) & 0x01010101u;
        unsigned m1 = __vcmpne4(v.y, 0u) & 0x01010101u;
        // (m * 0x01020408) >> 24 packs 4 byte-flags into 4 bits
        bits  = ((m0 * 0x01020408u) >> 24)
              | (((m1 * 0x01020408u) >> 24) << 4);
    }

    const int m   = __ldg(mask_size + s);
    const float mv = (float)__ldg(mask_value);

    // ---- local "last start index" within chunk ----
    int local_last = bits ? (t0 + 31 - __clz(bits)) : -1;

    // ---- block-wide exclusive max-scan over per-thread local_last ----
    int v = local_last;
    const int lane = tid & 31, wid = tid >> 5;
    #pragma unroll
    for (int off = 1; off < 32; off <<= 1) {
        int u = __shfl_up_sync(0xffffffffu, v, off);
        if (lane >= off) v = max(v, u);
    }
    __shared__ int wmax[NWARP];
    if (lane == 31) wmax[wid] = v;
    __syncthreads();
    int incl_prev = __shfl_up_sync(0xffffffffu, v, 1);  // inclusive scan of lane-1
    int excl = (lane == 0) ? -1 : incl_prev;
    #pragma unroll
    for (int w = 0; w < NWARP; w++)
        if (w < wid) excl = max(excl, wmax[w]);

    // ---- compute out / mask with carried last-start ----
    float4* ov  = (float4*)(out + base + t0);
    float4* mov = mask_out ? (float4*)(mask_out + base + t0) : nullptr;

    float4 xr[2] = {xx0, xx1};
    int cur = excl;
    #pragma unroll
    for (int j = 0; j < 2; j++) {
        const float* xa = (const float*)&xr[j];
        float o[4], mk[4];
        #pragma unroll
        for (int i = 0; i < 4; i++) {
            int k = j * 4 + i;
            int t = t0 + k;
            if ((bits >> k) & 1u) cur = t;
            int lo = t - m; if (lo < 0) lo = 0;
            bool msk = (cur >= lo);           // cur == -1 always fails (lo >= 0)
            mk[i] = msk ? 1.0f : 0.0f;
            o[i]  = msk ? mv : xa[i];
        }
        float4 ot = {o[0], o[1], o[2], o[3]};
        __stcs(ov + j, ot);
        if (mov) { float4 mt = {mk[0], mk[1], mk[2], mk[3]}; __stcs(mov + j, mt); }
    }
}

extern "C" void kernel_launch(void* const* d_in, const int* in_sizes, int n_in,
                              void* d_out, int out_size) {
    const float*         x     = (const float*)d_in[0];
    const unsigned char* idx   = (const unsigned char*)d_in[1];
    const int*           msize = (const int*)d_in[2];
    const int*           mval  = (const int*)d_in[3];
    float* out = (float*)d_out;

    const int T = 4096;
    const int N = in_sizes[0];          // B*S*T
    const int S = in_sizes[2];          // 128
    const int rows = N / T;             // B*S = 8192

    // Tuple output (out, mask) -> concatenated float32 if out_size covers both.
    float* mask_out = (out_size >= 2 * N) ? (out + (long long)N) : nullptr;

    probe_kernel<<<1, 256>>>((const uint4*)idx);
    seg_mask_kernel<<<rows, TPB>>>(x, idx, msize, mval, out, mask_out, S, T);
}

// round 4
// speedup vs baseline: 2.2698x; 1.0043x over previous
#include <cuda_runtime.h>
#include <cuda_bf16.h>

#define TPB 512
#define EPT 8    // elements per thread; TPB*EPT == T == 4096
#define NWARP (TPB / 32)

// Flag decided by the probe kernel: 1 => idx_mask buffer holds int32 0/1,
// 0 => it holds 1-byte bools.
__device__ int g_idx_is_int32;

// Minimal vectorized probe over the first 4KB: int32 0/1 flags have every
// byte at (pos % 4 != 0) equal to zero -> (w & 0xFFFFFF00) == 0 for every
// word. 5%-dense bool bytes violate this ~150 times in 4KB.
__global__ void probe_kernel(const uint4* __restrict__ p) {
    uint4 v = p[threadIdx.x];                 // 256 threads x 16B = 4KB
    unsigned local = (v.x & 0xFFFFFF00u) | (v.y & 0xFFFFFF00u) |
                     (v.z & 0xFFFFFF00u) | (v.w & 0xFFFFFF00u);
    int any = __syncthreads_or(local != 0);
    if (threadIdx.x == 0) g_idx_is_int32 = any ? 0 : 1;
}

__global__ __launch_bounds__(TPB, 4) void seg_mask_kernel(
    const float* __restrict__ x,
    const unsigned char* __restrict__ idx8,   // bool OR int32 flags, per g_idx_is_int32
    const int* __restrict__ mask_size,        // [S]
    const int* __restrict__ mask_value,       // scalar
    float* __restrict__ out,                  // [rows*T]
    float* __restrict__ mask_out,             // [rows*T] or nullptr
    int S, int T, int rows)
{
    const int tid  = threadIdx.x;
    const int lane = tid & 31, wid = tid >> 5;
    const int t0   = tid * EPT;
    const float mv = (float)__ldg(mask_value);
    const int is_i32 = g_idx_is_int32;

    // Double-buffered cross-warp scan scratch: one barrier per row.
    __shared__ int wmax[2][NWARP];

    int parity = 0;
    for (int row = blockIdx.x; row < rows; row += gridDim.x, parity ^= 1) {
        const int s = row % S;
        const long long base = (long long)row * T;

        // ---- front-batch ALL loads (flags + x) ----
        unsigned int bits;                    // bit i = flag at t0+i (8 bits)
        float4 xx0, xx1;
        const float4* xv = (const float4*)(x + base + t0);

        if (is_i32) {
            const int4* ip = (const int4*)((const int*)idx8 + base + t0);
            int4 a = __ldcs(ip + 0);
            int4 b = __ldcs(ip + 1);
            xx0 = __ldcs(xv + 0); xx1 = __ldcs(xv + 1);
            bits  = ((unsigned)(a.x != 0) << 0) | ((unsigned)(a.y != 0) << 1)
                  | ((unsigned)(a.z != 0) << 2) | ((unsigned)(a.w != 0) << 3)
                  | ((unsigned)(b.x != 0) << 4) | ((unsigned)(b.y != 0) << 5)
                  | ((unsigned)(b.z != 0) << 6) | ((unsigned)(b.w != 0) << 7);
        } else {
            uint2 v2 = __ldcs((const uint2*)(idx8 + base + t0));
            xx0 = __ldcs(xv + 0); xx1 = __ldcs(xv + 1);
            unsigned m0 = __vcmpne4(v2.x, 0u) & 0x01010101u;
            unsigned m1 = __vcmpne4(v2.y, 0u) & 0x01010101u;
            bits  = ((m0 * 0x01020408u) >> 24)
                  | (((m1 * 0x01020408u) >> 24) << 4);
        }

        const int m = __ldg(mask_size + s);

        // ---- local "last start index" within chunk ----
        int v = bits ? (t0 + 31 - __clz(bits)) : -1;

        // ---- block-wide exclusive max-scan ----
        #pragma unroll
        for (int off = 1; off < 32; off <<= 1) {
            int u = __shfl_up_sync(0xffffffffu, v, off);
            if (lane >= off) v = max(v, u);
        }
        if (lane == 31) wmax[parity][wid] = v;
        __syncthreads();
        int incl_prev = __shfl_up_sync(0xffffffffu, v, 1);
        int excl = (lane == 0) ? -1 : incl_prev;
        #pragma unroll
        for (int w = 0; w < NWARP; w++)
            if (w < wid) excl = max(excl, wmax[parity][w]);

        // ---- compute out / mask with carried last-start ----
        float4* ov  = (float4*)(out + base + t0);
        float4* mov = mask_out ? (float4*)(mask_out + base + t0) : nullptr;

        float4 xr[2] = {xx0, xx1};
        int cur = excl;
        #pragma unroll
        for (int j = 0; j < 2; j++) {
            const float* xa = (const float*)&xr[j];
            float o[4], mk[4];
            #pragma unroll
            for (int i = 0; i < 4; i++) {
                int k = j * 4 + i;
                int t = t0 + k;
                if ((bits >> k) & 1u) cur = t;
                int lo = t - m; if (lo < 0) lo = 0;
                bool msk = (cur >= lo);       // cur == -1 always fails (lo >= 0)
                mk[i] = msk ? 1.0f : 0.0f;
                o[i]  = msk ? mv : xa[i];
            }
            float4 ot = {o[0], o[1], o[2], o[3]};
            __stcs(ov + j, ot);
            if (mov) { float4 mt = {mk[0], mk[1], mk[2], mk[3]}; __stcs(mov + j, mt); }
        }
        // no trailing barrier: next iteration writes wmax[parity^1],
        // and the next __syncthreads() orders it against stragglers.
    }
}

extern "C" void kernel_launch(void* const* d_in, const int* in_sizes, int n_in,
                              void* d_out, int out_size) {
    const float*         x     = (const float*)d_in[0];
    const unsigned char* idx   = (const unsigned char*)d_in[1];
    const int*           msize = (const int*)d_in[2];
    const int*           mval  = (const int*)d_in[3];
    float* out = (float*)d_out;

    const int T = 4096;
    const int N = in_sizes[0];          // B*S*T
    const int S = in_sizes[2];          // 128
    const int rows = N / T;             // B*S = 8192

    // Tuple output (out, mask) -> concatenated float32 if out_size covers both.
    float* mask_out = (out_size >= 2 * N) ? (out + (long long)N) : nullptr;

    // Persistent grid: 4 CTAs per SM (forced by __launch_bounds__(512, 4)).
    int sms = 148;
    cudaDeviceGetAttribute(&sms, cudaDevAttrMultiProcessorCount, 0);
    int grid = sms * 4;
    if (grid > rows) grid = rows;

    probe_kernel<<<1, 256>>>((const uint4*)idx);
    seg_mask_kernel<<<grid, TPB>>>(x, idx, msize, mval, out, mask_out, S, T, rows);
}